// round 3
// baseline (speedup 1.0000x reference)
#include <cuda_runtime.h>
#include <cuda_bf16.h>
#include <cstdint>

// Problem constants
#define BB 2
#define TT 16
#define CC 30
#define HH 64
#define WW 64
#define NB 32            // B*T images
#define HP 66            // padded
#define WP 66
#define NK 9             // 3x3 kernel positions
#define OC90 90
#define CK 270           // 30*9
#define HWSZ 4096        // 64*64
#define PLANEP 4356      // 66*66
#define SPEC_BLOCKS 960  // 2*30*16

// ---------- scratch (device globals; no dynamic allocation allowed) ----------
__device__ float g_xp[NB * CC * PLANEP];          // padded + reindexed input
__device__ float g_off[NB * 18 * HWSZ];           // offsets
__device__ float g_m[NB * NK * HWSZ];             // sigmoid mask
__device__ float g_out30[NB * CC * HWSZ];         // after deform+einsum+comp
__device__ float g_out2[BB * TT * CC * HWSZ];     // after spec conv
__device__ float g_psum[SPEC_BLOCKS * 16];
__device__ float g_psumsq[SPEC_BLOCKS * 16];
__device__ float g_scale[16];
__device__ float g_shift[16];

// ---------------------------------------------------------------------------
// Kernel 1: build padded xp with the transpose(0,2,1,3,4).reshape batch shuffle
// xr[n][c] maps to x[b0][t0][c0] where f=n*30+c, b0=f/480, c0=(f%480)/16, t0=f%16
// ---------------------------------------------------------------------------
__global__ void k_pad(const float* __restrict__ x) {
    int idx = blockIdx.x * blockDim.x + threadIdx.x;
    const int total = NB * CC * PLANEP;
    if (idx >= total) return;
    int wp = idx % WP;
    int t1 = idx / WP;
    int hp = t1 % HP;
    int t2 = t1 / HP;
    int c  = t2 % CC;
    int n  = t2 / CC;
    float v = 0.f;
    if (hp >= 1 && hp <= HH && wp >= 1 && wp <= WW) {
        int f  = n * CC + c;
        int b0 = f / 480;
        int r  = f - b0 * 480;
        int c0 = r / 16;
        int t0 = r - c0 * 16;
        v = x[(((b0 * TT + t0) * CC + c0) * HH + (hp - 1)) * WW + (wp - 1)];
    }
    g_xp[idx] = v;
}

// ---------------------------------------------------------------------------
// Kernel 2: fused offset(18ch) + mask(9ch) 3x3 conv, pad=1, direct smem-tiled
// smem: input tile [30][18][19] + weights [30][9][28]
// ---------------------------------------------------------------------------
#define SM2_IN   (30 * 18 * 19)          // 10260 floats
#define SM2_W    (30 * 9 * 28)           // 7560 floats
#define SMEM2_BYTES ((SM2_IN + SM2_W) * 4)

__global__ __launch_bounds__(256, 2) void k_offmask(
    const float* __restrict__ p_w, const float* __restrict__ p_b,
    const float* __restrict__ m_w, const float* __restrict__ m_b)
{
    extern __shared__ float sm2[];
    float* sIn = sm2;              // [30][18][19]
    float* wsm = sm2 + SM2_IN;     // [(c*9+ij)*28 + oc]

    const int tid = threadIdx.x;
    const int n  = blockIdx.z;
    const int h0 = blockIdx.y * 16;
    const int w0 = blockIdx.x * 16;

    // load input tile: padded rows h0..h0+17, cols w0..w0+17
    const float* xpn = g_xp + n * CC * PLANEP;
    for (int idx = tid; idx < 30 * 324; idx += 256) {
        int c   = idx / 324;
        int rem = idx - c * 324;
        int r   = rem / 18;
        int col = rem - r * 18;
        sIn[c * 342 + r * 19 + col] = xpn[c * PLANEP + (h0 + r) * WP + (w0 + col)];
    }
    // load weights: oc<18 -> p_w, oc in [18,27) -> m_w, oc==27 -> 0 pad
    for (int idx = tid; idx < SM2_W; idx += 256) {
        int oc  = idx % 28;
        int cij = idx / 28;          // c*9 + ij
        float wv = 0.f;
        if (oc < 18)       wv = p_w[oc * 270 + cij];
        else if (oc < 27)  wv = m_w[(oc - 18) * 270 + cij];
        wsm[cij * 28 + oc] = wv;
    }
    __syncthreads();

    const int ty = tid >> 4;
    const int tx = tid & 15;
    float acc[28];
#pragma unroll
    for (int i = 0; i < 28; i++) acc[i] = 0.f;

    for (int c = 0; c < 30; c++) {
        const float* row = sIn + c * 342;
#pragma unroll
        for (int i = 0; i < 3; i++) {
#pragma unroll
            for (int j = 0; j < 3; j++) {
                float v = row[(ty + i) * 19 + (tx + j)];
                const float4* w4 = reinterpret_cast<const float4*>(&wsm[(c * 9 + i * 3 + j) * 28]);
#pragma unroll
                for (int u = 0; u < 7; u++) {
                    float4 wv = w4[u];
                    acc[u * 4 + 0] += v * wv.x;
                    acc[u * 4 + 1] += v * wv.y;
                    acc[u * 4 + 2] += v * wv.z;
                    acc[u * 4 + 3] += v * wv.w;
                }
            }
        }
    }

    const int hw = (h0 + ty) * WW + (w0 + tx);
#pragma unroll
    for (int oc = 0; oc < 18; oc++)
        g_off[(n * 18 + oc) * HWSZ + hw] = acc[oc] + p_b[oc];
#pragma unroll
    for (int q = 0; q < 9; q++) {
        float z = acc[18 + q] + m_b[q];
        g_m[(n * 9 + q) * HWSZ + hw] = 1.f / (1.f + __expf(-z));
    }
}

// ---------------------------------------------------------------------------
// Kernel 3: persistent deform-sample + einsum(270x90) + fused 1x1 comp(90->30)
// per tile of 64 pixels (8x8). smem layout (bytes):
//   Wsm    [270][96]  : 103680
//   sS     [270][64]  :  69120   (reused as out90 [96][65] in epilogue)
//   w4s    [9][64] f4 :   9216
//   crd    [9][64] us4:   4608
//   compsm [90][32]   :  11520
// total 198144
// ---------------------------------------------------------------------------
#define SM3_W_F    (CK * 96)
#define SM3_S_F    (CK * 64)
#define SMEM3_BYTES (SM3_W_F * 4 + SM3_S_F * 4 + NK * 64 * 16 + NK * 64 * 8 + 90 * 32 * 4)

__global__ __launch_bounds__(256, 1) void k_main(
    const float* __restrict__ conv_w, const float* __restrict__ comp_w)
{
    extern __shared__ float sm3[];
    float*   Wsm    = sm3;                                    // [ck][96]
    float*   sS     = sm3 + SM3_W_F;                          // [ck][64]
    float4*  w4s    = reinterpret_cast<float4*>(sm3 + SM3_W_F + SM3_S_F);
    ushort4* crd    = reinterpret_cast<ushort4*>(reinterpret_cast<char*>(w4s) + NK * 64 * 16);
    float*   compsm = reinterpret_cast<float*>(reinterpret_cast<char*>(crd) + NK * 64 * 8);

    const int tid = threadIdx.x;

    // --- load weights once per block (persistent) ---
    for (int idx = tid; idx < OC90 * CK; idx += 256) {
        int o = idx / CK, ck = idx - o * CK;
        Wsm[ck * 96 + o] = conv_w[idx];          // coalesced read
    }
    for (int idx = tid; idx < CK * 6; idx += 256) {
        int ck = idx / 6, o = 90 + (idx - ck * 6);
        Wsm[ck * 96 + o] = 0.f;
    }
    for (int idx = tid; idx < 90 * 32; idx += 256) {
        int o = idx >> 5, c = idx & 31;
        compsm[idx] = (c < 30) ? comp_w[c * 90 + o] : 0.f;
    }
    __syncthreads();

    const int ig = tid >> 4;     // pixel group 0..15 (4 px each)
    const int jg = tid & 15;     // oc group 0..15 (6 oc each)

    for (int work = blockIdx.x; work < NB * 64; work += gridDim.x) {
        const int n    = work >> 6;
        const int tile = work & 63;
        const int hb   = (tile >> 3) << 3;
        const int wb   = (tile & 7) << 3;

        // ---- Phase A1: bilinear params per (k, pixel) ----
        for (int idx = tid; idx < NK * 64; idx += 256) {
            int k  = idx >> 6;
            int pp = idx & 63;
            int h  = hb + (pp >> 3);
            int w  = wb + (pp & 7);
            int hw = h * WW + w;
            float ox = g_off[(n * 18 + k) * HWSZ + hw];
            float oy = g_off[(n * 18 + 9 + k) * HWSZ + hw];
            float mv = g_m[(n * 9 + k) * HWSZ + hw];
            int ki = k / 3, kj = k - ki * 3;
            float pxc = ox + (float)(ki - 1 + h + 1);
            float pyc = oy + (float)(kj - 1 + w + 1);
            float fx = floorf(pxc), fy = floorf(pyc);
            int x1 = max(0, min(65, (int)fx));
            int y1 = max(0, min(65, (int)fy));
            int x2 = max(0, min(65, (int)fx + 1));
            int y2 = max(0, min(65, (int)fy + 1));
            float cx = fminf(fmaxf(pxc, 0.f), 65.f);
            float cy = fminf(fmaxf(pyc, 0.f), 65.f);
            float ax = 1.f + ((float)x1 - cx);   // g_lt x-part
            float bx = 1.f - ((float)x2 - cx);   // g_rb x-part
            float ay = 1.f + ((float)y1 - cy);
            float by = 1.f - ((float)y2 - cy);
            w4s[idx] = make_float4(ax * ay * mv, bx * by * mv, ax * by * mv, bx * ay * mv);
            crd[idx] = make_ushort4((unsigned short)x1, (unsigned short)y1,
                                    (unsigned short)x2, (unsigned short)y2);
        }
        __syncthreads();

        // ---- Phase A2: gather into s[ck][px] ----
        {
            const float* xpn = g_xp + n * CC * PLANEP;
            for (int idx = tid; idx < CK * 64; idx += 256) {
                int ck = idx >> 6;
                int pp = idx & 63;
                int c  = ck / 9;
                int k  = ck - c * 9;
                float4  wv = w4s[k * 64 + pp];
                ushort4 q  = crd[k * 64 + pp];
                const float* bp = xpn + c * PLANEP;
                int r1 = (int)q.x * WP;
                int r2 = (int)q.z * WP;
                float v = wv.x * bp[r1 + q.y] + wv.y * bp[r2 + q.w]
                        + wv.z * bp[r1 + q.w] + wv.w * bp[r2 + q.y];
                sS[ck * 64 + pp] = v;
            }
        }
        __syncthreads();

        // ---- Phase B: 64x96 x K=270 SGEMM, thread tile 4px x 6oc ----
        float acc[4][6];
#pragma unroll
        for (int p = 0; p < 4; p++)
#pragma unroll
            for (int q = 0; q < 6; q++) acc[p][q] = 0.f;

        const float* sp = sS + (ig << 2);
        const float* wp = Wsm + jg * 6;
#pragma unroll 3
        for (int ck = 0; ck < CK; ck++) {
            float4 sv = *reinterpret_cast<const float4*>(sp + ck * 64);
            const float* wr = wp + ck * 96;
            float2 wa = *reinterpret_cast<const float2*>(wr);
            float2 wb2 = *reinterpret_cast<const float2*>(wr + 2);
            float2 wc = *reinterpret_cast<const float2*>(wr + 4);
            float s4[4] = {sv.x, sv.y, sv.z, sv.w};
            float wv6[6] = {wa.x, wa.y, wb2.x, wb2.y, wc.x, wc.y};
#pragma unroll
            for (int p = 0; p < 4; p++)
#pragma unroll
                for (int q = 0; q < 6; q++)
                    acc[p][q] += s4[p] * wv6[q];
        }
        __syncthreads();   // done reading sS; about to overwrite it

        // ---- write out90 to smem (stride 65, conflict-free) ----
        float* o90 = sS;
#pragma unroll
        for (int q = 0; q < 6; q++)
#pragma unroll
            for (int p = 0; p < 4; p++)
                o90[(jg * 6 + q) * 65 + (ig << 2) + p] = acc[p][q];
        __syncthreads();

        // ---- fused 1x1 comp: out30[c] = sum_o comp_w[c][o]*out90[o] ----
        {
            int pp = tid & 63;
            int cg = tid >> 6;      // 0..3, 8 channels each
            float a8[8];
#pragma unroll
            for (int q = 0; q < 8; q++) a8[q] = 0.f;
            const float* op  = o90 + pp;
            const float* cwp = compsm + (cg << 3);
#pragma unroll 6
            for (int o = 0; o < 90; o++) {
                float v = op[o * 65];
                float4 c0 = *reinterpret_cast<const float4*>(cwp + (o << 5));
                float4 c1 = *reinterpret_cast<const float4*>(cwp + (o << 5) + 4);
                a8[0] += v * c0.x; a8[1] += v * c0.y; a8[2] += v * c0.z; a8[3] += v * c0.w;
                a8[4] += v * c1.x; a8[5] += v * c1.y; a8[6] += v * c1.z; a8[7] += v * c1.w;
            }
            int h = hb + (pp >> 3), w = wb + (pp & 7);
            int c0i = cg << 3;
#pragma unroll
            for (int q = 0; q < 8; q++) {
                int c = c0i + q;
                if (c < 30)
                    g_out30[(n * CC + c) * HWSZ + h * WW + w] = a8[q];
            }
        }
        __syncthreads();   // before next tile reuses smem
    }
}

// ---------------------------------------------------------------------------
// Kernel 4: spec conv (T as channels, conv over C dim, kernel 3 pad 1)
//           + deterministic per-block BN partial sums
// grid: 960 blocks = (b, c, hw-chunk of 256)
// ---------------------------------------------------------------------------
__global__ __launch_bounds__(256) void k_spec(const float* __restrict__ spec_w) {
    __shared__ float sw[768];        // [to][ti][d]
    __shared__ float rsum[8][16];
    __shared__ float rsq[8][16];

    const int tid = threadIdx.x;
    for (int i = tid; i < 768; i += 256) sw[i] = spec_w[i];
    __syncthreads();

    const int bidx  = blockIdx.x;
    const int chunk = bidx & 15;
    const int c     = (bidx >> 4) % 30;
    const int b     = bidx / 480;
    const int px    = (chunk << 8) + tid;

    float acc[16];
#pragma unroll
    for (int t = 0; t < 16; t++) acc[t] = 0.f;

#pragma unroll 4
    for (int ti = 0; ti < 16; ti++) {
        const float* base = g_out30 + ((b * 16 + ti) * CC) * HWSZ + px;
        float v0 = (c > 0)  ? base[(c - 1) * HWSZ] : 0.f;
        float v1 = base[c * HWSZ];
        float v2 = (c < 29) ? base[(c + 1) * HWSZ] : 0.f;
        const float* swp = sw + ti * 3;
#pragma unroll
        for (int to = 0; to < 16; to++) {
            float a = acc[to];
            a += v0 * swp[to * 48 + 0];
            a += v1 * swp[to * 48 + 1];
            a += v2 * swp[to * 48 + 2];
            acc[to] = a;
        }
    }

    const int lane = tid & 31;
    const int wid  = tid >> 5;
#pragma unroll
    for (int to = 0; to < 16; to++) {
        g_out2[(((b * 16 + to) * CC + c) << 12) + px] = acc[to];
        float s  = acc[to];
        float q2 = acc[to] * acc[to];
#pragma unroll
        for (int off = 16; off; off >>= 1) {
            s  += __shfl_down_sync(0xffffffffu, s, off);
            q2 += __shfl_down_sync(0xffffffffu, q2, off);
        }
        if (lane == 0) { rsum[wid][to] = s; rsq[wid][to] = q2; }
    }
    __syncthreads();
    if (tid < 16) {
        float s = 0.f, q2 = 0.f;
#pragma unroll
        for (int w8 = 0; w8 < 8; w8++) { s += rsum[w8][tid]; q2 += rsq[w8][tid]; }
        g_psum[bidx * 16 + tid]   = s;
        g_psumsq[bidx * 16 + tid] = q2;
    }
}

// ---------------------------------------------------------------------------
// Kernel 5: reduce partials -> per-channel scale/shift (16 blocks, one per to)
// ---------------------------------------------------------------------------
__global__ void k_stats(const float* __restrict__ bn_g, const float* __restrict__ bn_b) {
    __shared__ float rs[256], rq[256];
    const int to = blockIdx.x, tid = threadIdx.x;
    float s = 0.f, q = 0.f;
    for (int i = tid; i < SPEC_BLOCKS; i += 256) {
        s += g_psum[i * 16 + to];
        q += g_psumsq[i * 16 + to];
    }
    rs[tid] = s; rq[tid] = q;
    __syncthreads();
    for (int off = 128; off; off >>= 1) {
        if (tid < off) { rs[tid] += rs[tid + off]; rq[tid] += rq[tid + off]; }
        __syncthreads();
    }
    if (tid == 0) {
        const float inv = 1.f / 245760.f;
        float mean = rs[0] * inv;
        float var  = rq[0] * inv - mean * mean;
        float rstd = rsqrtf(var + 1e-5f);
        float sc   = bn_g[to] * rstd;
        g_scale[to] = sc;
        g_shift[to] = bn_b[to] - mean * sc;
    }
}

// ---------------------------------------------------------------------------
// Kernel 6: normalize + affine + relu
// ---------------------------------------------------------------------------
__global__ void k_final(float* __restrict__ out) {
    int idx = blockIdx.x * blockDim.x + threadIdx.x;
    const int total = BB * TT * CC * HWSZ;
    if (idx >= total) return;
    int to = (idx / 122880) & 15;    // (b*16+to) % 16
    float v = g_out2[idx] * g_scale[to] + g_shift[to];
    out[idx] = fmaxf(v, 0.f);
}

// ---------------------------------------------------------------------------
extern "C" void kernel_launch(void* const* d_in, const int* in_sizes, int n_in,
                              void* d_out, int out_size)
{
    const float* x      = (const float*)d_in[0];
    const float* p_w    = (const float*)d_in[1];
    const float* p_b    = (const float*)d_in[2];
    const float* m_w    = (const float*)d_in[3];
    const float* m_b    = (const float*)d_in[4];
    const float* conv_w = (const float*)d_in[5];
    const float* comp_w = (const float*)d_in[6];
    const float* spec_w = (const float*)d_in[7];
    const float* bn_g   = (const float*)d_in[8];
    const float* bn_b   = (const float*)d_in[9];
    float* out = (float*)d_out;

    cudaFuncSetAttribute(k_offmask, cudaFuncAttributeMaxDynamicSharedMemorySize, SMEM2_BYTES);
    cudaFuncSetAttribute(k_main,    cudaFuncAttributeMaxDynamicSharedMemorySize, SMEM3_BYTES);

    // 1. padded + reindexed input
    {
        int total = NB * CC * PLANEP;
        k_pad<<<(total + 255) / 256, 256>>>(x);
    }
    // 2. offset + mask conv
    k_offmask<<<dim3(4, 4, NB), 256, SMEM2_BYTES>>>(p_w, p_b, m_w, m_b);
    // 3. deform sample + einsum + comp (persistent)
    k_main<<<152, 256, SMEM3_BYTES>>>(conv_w, comp_w);
    // 4. spec conv + BN partials
    k_spec<<<SPEC_BLOCKS, 256>>>(spec_w);
    // 5. BN stats
    k_stats<<<16, 256>>>(bn_g, bn_b);
    // 6. normalize + relu
    {
        int total = BB * TT * CC * HWSZ;
        k_final<<<(total + 255) / 256, 256>>>(out);
    }
}

// round 6
// speedup vs baseline: 1.0576x; 1.0576x over previous
#include <cuda_runtime.h>
#include <cuda_bf16.h>
#include <cstdint>

// Problem constants
#define BB 2
#define TT 16
#define CC 30
#define HH 64
#define WW 64
#define NB 32            // B*T images
#define HP 66            // padded
#define WP 66
#define NK 9             // 3x3 kernel positions
#define OC90 90
#define CK 270           // 30*9
#define HWSZ 4096        // 64*64
#define PLANEP 4356      // 66*66
#define SPEC_BLOCKS 960  // 2*30*16

// ---------- scratch (device globals; no dynamic allocation allowed) ----------
__device__ float g_xp[NB * CC * PLANEP];          // padded + reindexed input
__device__ float g_off[NB * 18 * HWSZ];           // offsets
__device__ float g_m[NB * NK * HWSZ];             // sigmoid mask
__device__ float g_out30[NB * CC * HWSZ];         // after deform+einsum+comp
__device__ float g_out2[BB * TT * CC * HWSZ];     // after spec conv
__device__ float g_psum[SPEC_BLOCKS * 16];
__device__ float g_psumsq[SPEC_BLOCKS * 16];
__device__ float g_scale[16];
__device__ float g_shift[16];

// ---------------------------------------------------------------------------
// Kernel 1: build padded xp with the transpose(0,2,1,3,4).reshape batch shuffle
// ---------------------------------------------------------------------------
__global__ void k_pad(const float* __restrict__ x) {
    int idx = blockIdx.x * blockDim.x + threadIdx.x;
    const int total = NB * CC * PLANEP;
    if (idx >= total) return;
    int wp = idx % WP;
    int t1 = idx / WP;
    int hp = t1 % HP;
    int t2 = t1 / HP;
    int c  = t2 % CC;
    int n  = t2 / CC;
    float v = 0.f;
    if (hp >= 1 && hp <= HH && wp >= 1 && wp <= WW) {
        int f  = n * CC + c;
        int b0 = f / 480;
        int r  = f - b0 * 480;
        int c0 = r / 16;
        int t0 = r - c0 * 16;
        v = x[(((b0 * TT + t0) * CC + c0) * HH + (hp - 1)) * WW + (wp - 1)];
    }
    g_xp[idx] = v;
}

// ---------------------------------------------------------------------------
// Kernel 2: fused offset(18ch) + mask(9ch) 3x3 conv, pad=1, direct smem-tiled
// ---------------------------------------------------------------------------
#define SM2_IN   (30 * 18 * 19)          // 10260 floats
#define SM2_W    (30 * 9 * 28)           // 7560 floats
#define SMEM2_BYTES ((SM2_IN + SM2_W) * 4)

__global__ __launch_bounds__(256, 2) void k_offmask(
    const float* __restrict__ p_w, const float* __restrict__ p_b,
    const float* __restrict__ m_w, const float* __restrict__ m_b)
{
    extern __shared__ float sm2[];
    float* sIn = sm2;              // [30][18][19]
    float* wsm = sm2 + SM2_IN;     // [(c*9+ij)*28 + oc]

    const int tid = threadIdx.x;
    const int n  = blockIdx.z;
    const int h0 = blockIdx.y * 16;
    const int w0 = blockIdx.x * 16;

    const float* xpn = g_xp + n * CC * PLANEP;
    for (int idx = tid; idx < 30 * 324; idx += 256) {
        int c   = idx / 324;
        int rem = idx - c * 324;
        int r   = rem / 18;
        int col = rem - r * 18;
        sIn[c * 342 + r * 19 + col] = xpn[c * PLANEP + (h0 + r) * WP + (w0 + col)];
    }
    for (int idx = tid; idx < SM2_W; idx += 256) {
        int oc  = idx % 28;
        int cij = idx / 28;          // c*9 + ij
        float wv = 0.f;
        if (oc < 18)       wv = p_w[oc * 270 + cij];
        else if (oc < 27)  wv = m_w[(oc - 18) * 270 + cij];
        wsm[cij * 28 + oc] = wv;
    }
    __syncthreads();

    const int ty = tid >> 4;
    const int tx = tid & 15;
    float acc[28];
#pragma unroll
    for (int i = 0; i < 28; i++) acc[i] = 0.f;

    for (int c = 0; c < 30; c++) {
        const float* row = sIn + c * 342;
#pragma unroll
        for (int i = 0; i < 3; i++) {
#pragma unroll
            for (int j = 0; j < 3; j++) {
                float v = row[(ty + i) * 19 + (tx + j)];
                const float4* w4 = reinterpret_cast<const float4*>(&wsm[(c * 9 + i * 3 + j) * 28]);
#pragma unroll
                for (int u = 0; u < 7; u++) {
                    float4 wv = w4[u];
                    acc[u * 4 + 0] += v * wv.x;
                    acc[u * 4 + 1] += v * wv.y;
                    acc[u * 4 + 2] += v * wv.z;
                    acc[u * 4 + 3] += v * wv.w;
                }
            }
        }
    }

    const int hw = (h0 + ty) * WW + (w0 + tx);
#pragma unroll
    for (int oc = 0; oc < 18; oc++)
        g_off[(n * 18 + oc) * HWSZ + hw] = acc[oc] + p_b[oc];
#pragma unroll
    for (int q = 0; q < 9; q++) {
        float z = acc[18 + q] + m_b[q];
        g_m[(n * 9 + q) * HWSZ + hw] = 1.f / (1.f + __expf(-z));
    }
}

// ---------------------------------------------------------------------------
// Kernel 3: persistent deform-sample + einsum(270x90) + fused 1x1 comp(90->30)
// 512 threads (4 warps/SMSP) for FMA issue saturation + gather MLP.
// smem layout unchanged (198144 B, occ 1).
// ---------------------------------------------------------------------------
#define SM3_W_F    (CK * 96)
#define SM3_S_F    (CK * 64)
#define SMEM3_BYTES (SM3_W_F * 4 + SM3_S_F * 4 + NK * 64 * 16 + NK * 64 * 8 + 90 * 32 * 4)
#define NT3 512

__global__ __launch_bounds__(NT3, 1) void k_main(
    const float* __restrict__ conv_w, const float* __restrict__ comp_w)
{
    extern __shared__ float sm3[];
    float*   Wsm    = sm3;                                    // [ck][96]
    float*   sS     = sm3 + SM3_W_F;                          // [ck][64]
    float4*  w4s    = reinterpret_cast<float4*>(sm3 + SM3_W_F + SM3_S_F);
    ushort4* crd    = reinterpret_cast<ushort4*>(reinterpret_cast<char*>(w4s) + NK * 64 * 16);
    float*   compsm = reinterpret_cast<float*>(reinterpret_cast<char*>(crd) + NK * 64 * 8);

    const int tid = threadIdx.x;

    // --- load weights once per block (persistent) ---
    for (int idx = tid; idx < OC90 * CK; idx += NT3) {
        int o = idx / CK, ck = idx - o * CK;
        Wsm[ck * 96 + o] = conv_w[idx];
    }
    for (int idx = tid; idx < CK * 6; idx += NT3) {
        int ck = idx / 6, o = 90 + (idx - ck * 6);
        Wsm[ck * 96 + o] = 0.f;
    }
    for (int idx = tid; idx < 90 * 32; idx += NT3) {
        int o = idx >> 5, c = idx & 31;
        compsm[idx] = (c < 30) ? comp_w[c * 90 + o] : 0.f;
    }
    __syncthreads();

    const int ig = tid >> 5;     // pixel group 0..15 (4 px each)
    const int jg = tid & 31;     // oc group 0..31 (3 oc each)

    for (int work = blockIdx.x; work < NB * 64; work += gridDim.x) {
        const int n    = work >> 6;
        const int tile = work & 63;
        const int hb   = (tile >> 3) << 3;
        const int wb   = (tile & 7) << 3;

        // ---- Phase A1: bilinear params per (k, pixel) ----
        for (int idx = tid; idx < NK * 64; idx += NT3) {
            int k  = idx >> 6;
            int pp = idx & 63;
            int h  = hb + (pp >> 3);
            int w  = wb + (pp & 7);
            int hw = h * WW + w;
            float ox = g_off[(n * 18 + k) * HWSZ + hw];
            float oy = g_off[(n * 18 + 9 + k) * HWSZ + hw];
            float mv = g_m[(n * 9 + k) * HWSZ + hw];
            int ki = k / 3, kj = k - ki * 3;
            float pxc = ox + (float)(ki - 1 + h + 1);
            float pyc = oy + (float)(kj - 1 + w + 1);
            float fx = floorf(pxc), fy = floorf(pyc);
            int x1 = max(0, min(65, (int)fx));
            int y1 = max(0, min(65, (int)fy));
            int x2 = max(0, min(65, (int)fx + 1));
            int y2 = max(0, min(65, (int)fy + 1));
            float cx = fminf(fmaxf(pxc, 0.f), 65.f);
            float cy = fminf(fmaxf(pyc, 0.f), 65.f);
            float ax = 1.f + ((float)x1 - cx);
            float bx = 1.f - ((float)x2 - cx);
            float ay = 1.f + ((float)y1 - cy);
            float by = 1.f - ((float)y2 - cy);
            w4s[idx] = make_float4(ax * ay * mv, bx * by * mv, ax * by * mv, bx * ay * mv);
            crd[idx] = make_ushort4((unsigned short)x1, (unsigned short)y1,
                                    (unsigned short)x2, (unsigned short)y2);
        }
        __syncthreads();

        // ---- Phase A2: gather into s[ck][px] ----
        {
            const float* xpn = g_xp + n * CC * PLANEP;
            for (int idx = tid; idx < CK * 64; idx += NT3) {
                int ck = idx >> 6;
                int pp = idx & 63;
                int c  = ck / 9;
                int k  = ck - c * 9;
                float4  wv = w4s[k * 64 + pp];
                ushort4 q  = crd[k * 64 + pp];
                const float* bp = xpn + c * PLANEP;
                int r1 = (int)q.x * WP;
                int r2 = (int)q.z * WP;
                float v = wv.x * bp[r1 + q.y] + wv.y * bp[r2 + q.w]
                        + wv.z * bp[r1 + q.w] + wv.w * bp[r2 + q.y];
                sS[ck * 64 + pp] = v;
            }
        }
        __syncthreads();

        // ---- Phase B: 64x96 x K=270 SGEMM, thread tile 4px x 3oc ----
        float acc[4][3];
#pragma unroll
        for (int p = 0; p < 4; p++)
#pragma unroll
            for (int q = 0; q < 3; q++) acc[p][q] = 0.f;

        const float* sp = sS + (ig << 2);
        const float* wp = Wsm + jg * 3;
#pragma unroll 5
        for (int ck = 0; ck < CK; ck++) {
            float4 sv = *reinterpret_cast<const float4*>(sp + ck * 64);
            const float* wr = wp + ck * 96;
            float w0 = wr[0], w1 = wr[1], w2 = wr[2];
            float s4[4] = {sv.x, sv.y, sv.z, sv.w};
#pragma unroll
            for (int p = 0; p < 4; p++) {
                acc[p][0] += s4[p] * w0;
                acc[p][1] += s4[p] * w1;
                acc[p][2] += s4[p] * w2;
            }
        }
        __syncthreads();   // done reading sS; about to overwrite it

        // ---- write out90 to smem (stride 65, conflict-free) ----
        float* o90 = sS;
#pragma unroll
        for (int q = 0; q < 3; q++)
#pragma unroll
            for (int p = 0; p < 4; p++)
                o90[(jg * 3 + q) * 65 + (ig << 2) + p] = acc[p][q];
        __syncthreads();

        // ---- fused 1x1 comp: out30[c] = sum_o comp_w[c][o]*out90[o] ----
        {
            int pp = tid & 63;
            int cg = tid >> 6;      // 0..7, 4 channels each
            float a4[4];
#pragma unroll
            for (int q = 0; q < 4; q++) a4[q] = 0.f;
            const float* op  = o90 + pp;
            const float* cwp = compsm + (cg << 2);
#pragma unroll 6
            for (int o = 0; o < 90; o++) {
                float v = op[o * 65];
                float4 c0 = *reinterpret_cast<const float4*>(cwp + (o << 5));
                a4[0] += v * c0.x; a4[1] += v * c0.y; a4[2] += v * c0.z; a4[3] += v * c0.w;
            }
            int h = hb + (pp >> 3), w = wb + (pp & 7);
            int c0i = cg << 2;
#pragma unroll
            for (int q = 0; q < 4; q++) {
                int c = c0i + q;
                if (c < 30)
                    g_out30[(n * CC + c) * HWSZ + h * WW + w] = a4[q];
            }
        }
        __syncthreads();   // before next tile reuses smem
    }
}

// ---------------------------------------------------------------------------
// Kernel 4: spec conv + BN partials.
// Weights repacked [ti][d][to16] -> 4x LDS.128 per (ti,d) instead of 16x LDS.32
// ---------------------------------------------------------------------------
__global__ __launch_bounds__(256) void k_spec(const float* __restrict__ spec_w) {
    __shared__ float sw2[768];       // [ti][d][to]
    __shared__ float rsum[8][16];
    __shared__ float rsq[8][16];

    const int tid = threadIdx.x;
    for (int i = tid; i < 768; i += 256) {
        int to = i / 48;
        int r  = i - to * 48;
        int ti = r / 3;
        int d  = r - ti * 3;
        sw2[(ti * 3 + d) * 16 + to] = spec_w[i];
    }
    __syncthreads();

    const int bidx  = blockIdx.x;
    const int chunk = bidx & 15;
    const int c     = (bidx >> 4) % 30;
    const int b     = bidx / 480;
    const int px    = (chunk << 8) + tid;

    float acc[16];
#pragma unroll
    for (int t = 0; t < 16; t++) acc[t] = 0.f;

    const float4* sw4 = reinterpret_cast<const float4*>(sw2);

#pragma unroll 4
    for (int ti = 0; ti < 16; ti++) {
        const float* base = g_out30 + ((b * 16 + ti) * CC) * HWSZ + px;
        float v0 = (c > 0)  ? base[(c - 1) * HWSZ] : 0.f;
        float v1 = base[c * HWSZ];
        float v2 = (c < 29) ? base[(c + 1) * HWSZ] : 0.f;
#pragma unroll
        for (int g = 0; g < 4; g++) {
            float4 a0 = sw4[(ti * 3 + 0) * 4 + g];
            float4 a1 = sw4[(ti * 3 + 1) * 4 + g];
            float4 a2 = sw4[(ti * 3 + 2) * 4 + g];
            acc[g * 4 + 0] += v0 * a0.x + v1 * a1.x + v2 * a2.x;
            acc[g * 4 + 1] += v0 * a0.y + v1 * a1.y + v2 * a2.y;
            acc[g * 4 + 2] += v0 * a0.z + v1 * a1.z + v2 * a2.z;
            acc[g * 4 + 3] += v0 * a0.w + v1 * a1.w + v2 * a2.w;
        }
    }

    const int lane = tid & 31;
    const int wid  = tid >> 5;
#pragma unroll
    for (int to = 0; to < 16; to++) {
        g_out2[(((b * 16 + to) * CC + c) << 12) + px] = acc[to];
        float s  = acc[to];
        float q2 = acc[to] * acc[to];
#pragma unroll
        for (int off = 16; off; off >>= 1) {
            s  += __shfl_down_sync(0xffffffffu, s, off);
            q2 += __shfl_down_sync(0xffffffffu, q2, off);
        }
        if (lane == 0) { rsum[wid][to] = s; rsq[wid][to] = q2; }
    }
    __syncthreads();
    if (tid < 16) {
        float s = 0.f, q2 = 0.f;
#pragma unroll
        for (int w8 = 0; w8 < 8; w8++) { s += rsum[w8][tid]; q2 += rsq[w8][tid]; }
        g_psum[bidx * 16 + tid]   = s;
        g_psumsq[bidx * 16 + tid] = q2;
    }
}

// ---------------------------------------------------------------------------
// Kernel 5: reduce partials -> per-channel scale/shift
// ---------------------------------------------------------------------------
__global__ void k_stats(const float* __restrict__ bn_g, const float* __restrict__ bn_b) {
    __shared__ float rs[256], rq[256];
    const int to = blockIdx.x, tid = threadIdx.x;
    float s = 0.f, q = 0.f;
    for (int i = tid; i < SPEC_BLOCKS; i += 256) {
        s += g_psum[i * 16 + to];
        q += g_psumsq[i * 16 + to];
    }
    rs[tid] = s; rq[tid] = q;
    __syncthreads();
    for (int off = 128; off; off >>= 1) {
        if (tid < off) { rs[tid] += rs[tid + off]; rq[tid] += rq[tid + off]; }
        __syncthreads();
    }
    if (tid == 0) {
        const float inv = 1.f / 245760.f;
        float mean = rs[0] * inv;
        float var  = rq[0] * inv - mean * mean;
        float rstd = rsqrtf(var + 1e-5f);
        float sc   = bn_g[to] * rstd;
        g_scale[to] = sc;
        g_shift[to] = bn_b[to] - mean * sc;
    }
}

// ---------------------------------------------------------------------------
// Kernel 6: normalize + affine + relu (float4; 122880 % 4 == 0 so the
// to-index is constant within each 4-aligned group)
// ---------------------------------------------------------------------------
__global__ void k_final(float* __restrict__ out) {
    int i4 = blockIdx.x * blockDim.x + threadIdx.x;
    const int total4 = (BB * TT * CC * HWSZ) / 4;
    if (i4 >= total4) return;
    int to = ((i4 * 4) / 122880) & 15;
    float sc = g_scale[to], sh = g_shift[to];
    float4 v = reinterpret_cast<const float4*>(g_out2)[i4];
    v.x = fmaxf(v.x * sc + sh, 0.f);
    v.y = fmaxf(v.y * sc + sh, 0.f);
    v.z = fmaxf(v.z * sc + sh, 0.f);
    v.w = fmaxf(v.w * sc + sh, 0.f);
    reinterpret_cast<float4*>(out)[i4] = v;
}

// ---------------------------------------------------------------------------
extern "C" void kernel_launch(void* const* d_in, const int* in_sizes, int n_in,
                              void* d_out, int out_size)
{
    const float* x      = (const float*)d_in[0];
    const float* p_w    = (const float*)d_in[1];
    const float* p_b    = (const float*)d_in[2];
    const float* m_w    = (const float*)d_in[3];
    const float* m_b    = (const float*)d_in[4];
    const float* conv_w = (const float*)d_in[5];
    const float* comp_w = (const float*)d_in[6];
    const float* spec_w = (const float*)d_in[7];
    const float* bn_g   = (const float*)d_in[8];
    const float* bn_b   = (const float*)d_in[9];
    float* out = (float*)d_out;

    cudaFuncSetAttribute(k_offmask, cudaFuncAttributeMaxDynamicSharedMemorySize, SMEM2_BYTES);
    cudaFuncSetAttribute(k_main,    cudaFuncAttributeMaxDynamicSharedMemorySize, SMEM3_BYTES);

    // 1. padded + reindexed input
    {
        int total = NB * CC * PLANEP;
        k_pad<<<(total + 255) / 256, 256>>>(x);
    }
    // 2. offset + mask conv
    k_offmask<<<dim3(4, 4, NB), 256, SMEM2_BYTES>>>(p_w, p_b, m_w, m_b);
    // 3. deform sample + einsum + comp (persistent)
    k_main<<<152, NT3, SMEM3_BYTES>>>(conv_w, comp_w);
    // 4. spec conv + BN partials
    k_spec<<<SPEC_BLOCKS, 256>>>(spec_w);
    // 5. BN stats
    k_stats<<<16, 256>>>(bn_g, bn_b);
    // 6. normalize + relu
    {
        int total4 = (BB * TT * CC * HWSZ) / 4;
        k_final<<<(total4 + 255) / 256, 256>>>(out);
    }
}

// round 9
// speedup vs baseline: 1.1220x; 1.0609x over previous
#include <cuda_runtime.h>
#include <cuda_bf16.h>
#include <cstdint>

// Problem constants
#define BB 2
#define TT 16
#define CC 30
#define HH 64
#define WW 64
#define NB 32            // B*T images
#define HP 66            // padded
#define WP 66
#define NK 9             // 3x3 kernel positions
#define OC90 90
#define CK 270           // 30*9
#define HWSZ 4096        // 64*64
#define PLANEP 4356      // 66*66
#define SPEC_BLOCKS 480  // 2*30*8 (float2 k_spec)

// ---------- scratch (device globals; no dynamic allocation allowed) ----------
__device__ float g_xp[NB * CC * PLANEP];          // padded + reindexed input
__device__ float g_off[NB * 18 * HWSZ];           // offsets
__device__ float g_m[NB * NK * HWSZ];             // sigmoid mask
__device__ float g_out30[NB * CC * HWSZ];         // after deform+einsum+comp
__device__ float g_out2[BB * TT * CC * HWSZ];     // after spec conv
__device__ float g_psum[SPEC_BLOCKS * 16];
__device__ float g_psumsq[SPEC_BLOCKS * 16];
__device__ float g_scale[16];
__device__ float g_shift[16];

// ---------------------------------------------------------------------------
// Kernel 1a/1b: build padded xp (split in two launches so k_main is launch #4,
// which is the slot ncu -s/-c captures)
// ---------------------------------------------------------------------------
__device__ __forceinline__ void pad_body(const float* __restrict__ x, int idx) {
    int wp = idx % WP;
    int t1 = idx / WP;
    int hp = t1 % HP;
    int t2 = t1 / HP;
    int c  = t2 % CC;
    int n  = t2 / CC;
    float v = 0.f;
    if (hp >= 1 && hp <= HH && wp >= 1 && wp <= WW) {
        int f  = n * CC + c;
        int b0 = f / 480;
        int r  = f - b0 * 480;
        int c0 = r / 16;
        int t0 = r - c0 * 16;
        v = x[(((b0 * TT + t0) * CC + c0) * HH + (hp - 1)) * WW + (wp - 1)];
    }
    g_xp[idx] = v;
}

#define PAD_TOTAL (NB * CC * PLANEP)
#define PAD_HALF  (PAD_TOTAL / 2)

__global__ void k_pad_a(const float* __restrict__ x) {
    int idx = blockIdx.x * blockDim.x + threadIdx.x;
    if (idx >= PAD_HALF) return;
    pad_body(x, idx);
}
__global__ void k_pad_b(const float* __restrict__ x) {
    int idx = PAD_HALF + blockIdx.x * blockDim.x + threadIdx.x;
    if (idx >= PAD_TOTAL) return;
    pad_body(x, idx);
}

// ---------------------------------------------------------------------------
// Kernel 2: fused offset(18ch) + mask(9ch) 3x3 conv, pad=1, direct smem-tiled
// ---------------------------------------------------------------------------
#define SM2_IN   (30 * 18 * 19)          // 10260 floats
#define SM2_W    (30 * 9 * 28)           // 7560 floats
#define SMEM2_BYTES ((SM2_IN + SM2_W) * 4)

__global__ __launch_bounds__(256, 2) void k_offmask(
    const float* __restrict__ p_w, const float* __restrict__ p_b,
    const float* __restrict__ m_w, const float* __restrict__ m_b)
{
    extern __shared__ float sm2[];
    float* sIn = sm2;              // [30][18][19]
    float* wsm = sm2 + SM2_IN;     // [(c*9+ij)*28 + oc]

    const int tid = threadIdx.x;
    const int n  = blockIdx.z;
    const int h0 = blockIdx.y * 16;
    const int w0 = blockIdx.x * 16;

    const float* xpn = g_xp + n * CC * PLANEP;
    for (int idx = tid; idx < 30 * 324; idx += 256) {
        int c   = idx / 324;
        int rem = idx - c * 324;
        int r   = rem / 18;
        int col = rem - r * 18;
        sIn[c * 342 + r * 19 + col] = xpn[c * PLANEP + (h0 + r) * WP + (w0 + col)];
    }
    for (int idx = tid; idx < SM2_W; idx += 256) {
        int oc  = idx % 28;
        int cij = idx / 28;          // c*9 + ij
        float wv = 0.f;
        if (oc < 18)       wv = p_w[oc * 270 + cij];
        else if (oc < 27)  wv = m_w[(oc - 18) * 270 + cij];
        wsm[cij * 28 + oc] = wv;
    }
    __syncthreads();

    const int ty = tid >> 4;
    const int tx = tid & 15;
    float acc[28];
#pragma unroll
    for (int i = 0; i < 28; i++) acc[i] = 0.f;

    for (int c = 0; c < 30; c++) {
        const float* row = sIn + c * 342;
#pragma unroll
        for (int i = 0; i < 3; i++) {
#pragma unroll
            for (int j = 0; j < 3; j++) {
                float v = row[(ty + i) * 19 + (tx + j)];
                const float4* w4 = reinterpret_cast<const float4*>(&wsm[(c * 9 + i * 3 + j) * 28]);
#pragma unroll
                for (int u = 0; u < 7; u++) {
                    float4 wv = w4[u];
                    acc[u * 4 + 0] += v * wv.x;
                    acc[u * 4 + 1] += v * wv.y;
                    acc[u * 4 + 2] += v * wv.z;
                    acc[u * 4 + 3] += v * wv.w;
                }
            }
        }
    }

    const int hw = (h0 + ty) * WW + (w0 + tx);
#pragma unroll
    for (int oc = 0; oc < 18; oc++)
        g_off[(n * 18 + oc) * HWSZ + hw] = acc[oc] + p_b[oc];
#pragma unroll
    for (int q = 0; q < 9; q++) {
        float z = acc[18 + q] + m_b[q];
        g_m[(n * 9 + q) * HWSZ + hw] = 1.f / (1.f + __expf(-z));
    }
}

// ---------------------------------------------------------------------------
// Kernel 3: persistent deform-sample + einsum(270x90) + fused 1x1 comp(90->30)
// 512 threads. A2 gather explicitly paired for MLP.
// ---------------------------------------------------------------------------
#define SM3_W_F    (CK * 96)
#define SM3_S_F    (CK * 64)
#define SMEM3_BYTES (SM3_W_F * 4 + SM3_S_F * 4 + NK * 64 * 16 + NK * 64 * 8 + 90 * 32 * 4)
#define NT3 512

__global__ __launch_bounds__(NT3, 1) void k_main(
    const float* __restrict__ conv_w, const float* __restrict__ comp_w)
{
    extern __shared__ float sm3[];
    float*   Wsm    = sm3;                                    // [ck][96]
    float*   sS     = sm3 + SM3_W_F;                          // [ck][64]
    float4*  w4s    = reinterpret_cast<float4*>(sm3 + SM3_W_F + SM3_S_F);
    ushort4* crd    = reinterpret_cast<ushort4*>(reinterpret_cast<char*>(w4s) + NK * 64 * 16);
    float*   compsm = reinterpret_cast<float*>(reinterpret_cast<char*>(crd) + NK * 64 * 8);

    const int tid = threadIdx.x;

    // --- load weights once per block (persistent) ---
    for (int idx = tid; idx < OC90 * CK; idx += NT3) {
        int o = idx / CK, ck = idx - o * CK;
        Wsm[ck * 96 + o] = conv_w[idx];
    }
    for (int idx = tid; idx < CK * 6; idx += NT3) {
        int ck = idx / 6, o = 90 + (idx - ck * 6);
        Wsm[ck * 96 + o] = 0.f;
    }
    for (int idx = tid; idx < 90 * 32; idx += NT3) {
        int o = idx >> 5, c = idx & 31;
        compsm[idx] = (c < 30) ? comp_w[c * 90 + o] : 0.f;
    }
    __syncthreads();

    const int ig = tid >> 5;     // pixel group 0..15 (4 px each)
    const int jg = tid & 31;     // oc group 0..31 (3 oc each)

    for (int work = blockIdx.x; work < NB * 64; work += gridDim.x) {
        const int n    = work >> 6;
        const int tile = work & 63;
        const int hb   = (tile >> 3) << 3;
        const int wb   = (tile & 7) << 3;

        // ---- Phase A1: bilinear params per (k, pixel) ----
        for (int idx = tid; idx < NK * 64; idx += NT3) {
            int k  = idx >> 6;
            int pp = idx & 63;
            int h  = hb + (pp >> 3);
            int w  = wb + (pp & 7);
            int hw = h * WW + w;
            float ox = g_off[(n * 18 + k) * HWSZ + hw];
            float oy = g_off[(n * 18 + 9 + k) * HWSZ + hw];
            float mv = g_m[(n * 9 + k) * HWSZ + hw];
            int ki = k / 3, kj = k - ki * 3;
            float pxc = ox + (float)(ki - 1 + h + 1);
            float pyc = oy + (float)(kj - 1 + w + 1);
            float fx = floorf(pxc), fy = floorf(pyc);
            int x1 = max(0, min(65, (int)fx));
            int y1 = max(0, min(65, (int)fy));
            int x2 = max(0, min(65, (int)fx + 1));
            int y2 = max(0, min(65, (int)fy + 1));
            float cx = fminf(fmaxf(pxc, 0.f), 65.f);
            float cy = fminf(fmaxf(pyc, 0.f), 65.f);
            float ax = 1.f + ((float)x1 - cx);
            float bx = 1.f - ((float)x2 - cx);
            float ay = 1.f + ((float)y1 - cy);
            float by = 1.f - ((float)y2 - cy);
            w4s[idx] = make_float4(ax * ay * mv, bx * by * mv, ax * by * mv, bx * ay * mv);
            crd[idx] = make_ushort4((unsigned short)x1, (unsigned short)y1,
                                    (unsigned short)x2, (unsigned short)y2);
        }
        __syncthreads();

        // ---- Phase A2: gather into s[ck][px], 2-way paired for MLP ----
        // CK*64 = 17280 = 16*1024 + 512 + 384
        {
            const float* xpn = g_xp + n * CC * PLANEP;

#define GATHER_LOAD(IDX, WV, P00, P10, P01, P11)                       \
            {                                                          \
                int ck_ = (IDX) >> 6;                                  \
                int pp_ = (IDX) & 63;                                  \
                int c_  = ck_ / 9;                                     \
                int k_  = ck_ - c_ * 9;                                \
                WV = w4s[k_ * 64 + pp_];                               \
                ushort4 q_ = crd[k_ * 64 + pp_];                       \
                const float* bp_ = xpn + c_ * PLANEP;                  \
                int r1_ = (int)q_.x * WP;                              \
                int r2_ = (int)q_.z * WP;                              \
                P00 = bp_[r1_ + q_.y];                                 \
                P10 = bp_[r2_ + q_.w];                                 \
                P01 = bp_[r1_ + q_.w];                                 \
                P11 = bp_[r2_ + q_.y];                                 \
            }

#pragma unroll 1
            for (int j = 0; j < 16; j++) {
                int i0 = tid + j * 1024;
                int i1 = i0 + 512;
                float4 wa, wb2;
                float a00, a10, a01, a11, b00, b10, b01, b11;
                GATHER_LOAD(i0, wa,  a00, a10, a01, a11);
                GATHER_LOAD(i1, wb2, b00, b10, b01, b11);
                sS[i0] = wa.x  * a00 + wa.y  * a10 + wa.z  * a01 + wa.w  * a11;
                sS[i1] = wb2.x * b00 + wb2.y * b10 + wb2.z * b01 + wb2.w * b11;
            }
            {
                int i0 = 16384 + tid;
                float4 wa;
                float a00, a10, a01, a11;
                GATHER_LOAD(i0, wa, a00, a10, a01, a11);
                sS[i0] = wa.x * a00 + wa.y * a10 + wa.z * a01 + wa.w * a11;
            }
            if (tid < 384) {
                int i0 = 16896 + tid;
                float4 wa;
                float a00, a10, a01, a11;
                GATHER_LOAD(i0, wa, a00, a10, a01, a11);
                sS[i0] = wa.x * a00 + wa.y * a10 + wa.z * a01 + wa.w * a11;
            }
#undef GATHER_LOAD
        }
        __syncthreads();

        // ---- Phase B: 64x96 x K=270 SGEMM, thread tile 4px x 3oc ----
        float acc[4][3];
#pragma unroll
        for (int p = 0; p < 4; p++)
#pragma unroll
            for (int q = 0; q < 3; q++) acc[p][q] = 0.f;

        const float* sp = sS + (ig << 2);
        const float* wp = Wsm + jg * 3;
#pragma unroll 5
        for (int ck = 0; ck < CK; ck++) {
            float4 sv = *reinterpret_cast<const float4*>(sp + ck * 64);
            const float* wr = wp + ck * 96;
            float w0 = wr[0], w1 = wr[1], w2 = wr[2];
            float s4[4] = {sv.x, sv.y, sv.z, sv.w};
#pragma unroll
            for (int p = 0; p < 4; p++) {
                acc[p][0] += s4[p] * w0;
                acc[p][1] += s4[p] * w1;
                acc[p][2] += s4[p] * w2;
            }
        }
        __syncthreads();   // done reading sS; about to overwrite it

        // ---- write out90 to smem (stride 65, conflict-free) ----
        float* o90 = sS;
#pragma unroll
        for (int q = 0; q < 3; q++)
#pragma unroll
            for (int p = 0; p < 4; p++)
                o90[(jg * 3 + q) * 65 + (ig << 2) + p] = acc[p][q];
        __syncthreads();

        // ---- fused 1x1 comp: out30[c] = sum_o comp_w[c][o]*out90[o] ----
        {
            int pp = tid & 63;
            int cg = tid >> 6;      // 0..7, 4 channels each
            float a4[4];
#pragma unroll
            for (int q = 0; q < 4; q++) a4[q] = 0.f;
            const float* op  = o90 + pp;
            const float* cwp = compsm + (cg << 2);
#pragma unroll 6
            for (int o = 0; o < 90; o++) {
                float v = op[o * 65];
                float4 c0 = *reinterpret_cast<const float4*>(cwp + (o << 5));
                a4[0] += v * c0.x; a4[1] += v * c0.y; a4[2] += v * c0.z; a4[3] += v * c0.w;
            }
            int h = hb + (pp >> 3), w = wb + (pp & 7);
            int c0i = cg << 2;
#pragma unroll
            for (int q = 0; q < 4; q++) {
                int c = c0i + q;
                if (c < 30)
                    g_out30[(n * CC + c) * HWSZ + h * WW + w] = a4[q];
            }
        }
        __syncthreads();   // before next tile reuses smem
    }
}

// ---------------------------------------------------------------------------
// Kernel 4: spec conv + BN partials. float2 per thread: halves LDG/issue count
// (profile showed L1tex-bound from the g_out30 LDG stream).
// grid: 480 blocks = (b, c, hw-chunk of 512)
// ---------------------------------------------------------------------------
__global__ __launch_bounds__(256) void k_spec(const float* __restrict__ spec_w) {
    __shared__ float sw2[768];       // [ti][d][to]
    __shared__ float rsum[8][16];
    __shared__ float rsq[8][16];

    const int tid = threadIdx.x;
    for (int i = tid; i < 768; i += 256) {
        int to = i / 48;
        int r  = i - to * 48;
        int ti = r / 3;
        int d  = r - ti * 3;
        sw2[(ti * 3 + d) * 16 + to] = spec_w[i];
    }
    __syncthreads();

    const int bidx  = blockIdx.x;
    const int chunk = bidx & 7;
    const int c     = (bidx >> 3) % 30;
    const int b     = bidx / 240;
    const int px    = (chunk << 9) + tid * 2;

    float2 acc[16];
#pragma unroll
    for (int t = 0; t < 16; t++) acc[t] = make_float2(0.f, 0.f);

    const float4* sw4 = reinterpret_cast<const float4*>(sw2);
    const float2 z2 = make_float2(0.f, 0.f);

#pragma unroll 4
    for (int ti = 0; ti < 16; ti++) {
        const float* base = g_out30 + (((b * 16 + ti) * CC + c) * HWSZ) + px;
        float2 v0 = (c > 0)  ? *reinterpret_cast<const float2*>(base - HWSZ) : z2;
        float2 v1 = *reinterpret_cast<const float2*>(base);
        float2 v2 = (c < 29) ? *reinterpret_cast<const float2*>(base + HWSZ) : z2;
#pragma unroll
        for (int g = 0; g < 4; g++) {
            float4 a0 = sw4[(ti * 3 + 0) * 4 + g];
            float4 a1 = sw4[(ti * 3 + 1) * 4 + g];
            float4 a2 = sw4[(ti * 3 + 2) * 4 + g];
            acc[g*4+0].x += v0.x*a0.x + v1.x*a1.x + v2.x*a2.x;
            acc[g*4+0].y += v0.y*a0.x + v1.y*a1.x + v2.y*a2.x;
            acc[g*4+1].x += v0.x*a0.y + v1.x*a1.y + v2.x*a2.y;
            acc[g*4+1].y += v0.y*a0.y + v1.y*a1.y + v2.y*a2.y;
            acc[g*4+2].x += v0.x*a0.z + v1.x*a1.z + v2.x*a2.z;
            acc[g*4+2].y += v0.y*a0.z + v1.y*a1.z + v2.y*a2.z;
            acc[g*4+3].x += v0.x*a0.w + v1.x*a1.w + v2.x*a2.w;
            acc[g*4+3].y += v0.y*a0.w + v1.y*a1.w + v2.y*a2.w;
        }
    }

    const int lane = tid & 31;
    const int wid  = tid >> 5;
#pragma unroll
    for (int to = 0; to < 16; to++) {
        *reinterpret_cast<float2*>(&g_out2[(((b * 16 + to) * CC + c) << 12) + px]) = acc[to];
        float s  = acc[to].x + acc[to].y;
        float q2 = acc[to].x * acc[to].x + acc[to].y * acc[to].y;
#pragma unroll
        for (int off = 16; off; off >>= 1) {
            s  += __shfl_down_sync(0xffffffffu, s, off);
            q2 += __shfl_down_sync(0xffffffffu, q2, off);
        }
        if (lane == 0) { rsum[wid][to] = s; rsq[wid][to] = q2; }
    }
    __syncthreads();
    if (tid < 16) {
        float s = 0.f, q2 = 0.f;
#pragma unroll
        for (int w8 = 0; w8 < 8; w8++) { s += rsum[w8][tid]; q2 += rsq[w8][tid]; }
        g_psum[bidx * 16 + tid]   = s;
        g_psumsq[bidx * 16 + tid] = q2;
    }
}

// ---------------------------------------------------------------------------
// Kernel 5: reduce partials -> per-channel scale/shift
// ---------------------------------------------------------------------------
__global__ void k_stats(const float* __restrict__ bn_g, const float* __restrict__ bn_b) {
    __shared__ float rs[256], rq[256];
    const int to = blockIdx.x, tid = threadIdx.x;
    float s = 0.f, q = 0.f;
    for (int i = tid; i < SPEC_BLOCKS; i += 256) {
        s += g_psum[i * 16 + to];
        q += g_psumsq[i * 16 + to];
    }
    rs[tid] = s; rq[tid] = q;
    __syncthreads();
    for (int off = 128; off; off >>= 1) {
        if (tid < off) { rs[tid] += rs[tid + off]; rq[tid] += rq[tid + off]; }
        __syncthreads();
    }
    if (tid == 0) {
        const float inv = 1.f / 245760.f;
        float mean = rs[0] * inv;
        float var  = rq[0] * inv - mean * mean;
        float rstd = rsqrtf(var + 1e-5f);
        float sc   = bn_g[to] * rstd;
        g_scale[to] = sc;
        g_shift[to] = bn_b[to] - mean * sc;
    }
}

// ---------------------------------------------------------------------------
// Kernel 6: normalize + affine + relu (float4; 122880 % 4 == 0)
// ---------------------------------------------------------------------------
__global__ void k_final(float* __restrict__ out) {
    int i4 = blockIdx.x * blockDim.x + threadIdx.x;
    const int total4 = (BB * TT * CC * HWSZ) / 4;
    if (i4 >= total4) return;
    int to = ((i4 * 4) / 122880) & 15;
    float sc = g_scale[to], sh = g_shift[to];
    float4 v = reinterpret_cast<const float4*>(g_out2)[i4];
    v.x = fmaxf(v.x * sc + sh, 0.f);
    v.y = fmaxf(v.y * sc + sh, 0.f);
    v.z = fmaxf(v.z * sc + sh, 0.f);
    v.w = fmaxf(v.w * sc + sh, 0.f);
    reinterpret_cast<float4*>(out)[i4] = v;
}

// ---------------------------------------------------------------------------
extern "C" void kernel_launch(void* const* d_in, const int* in_sizes, int n_in,
                              void* d_out, int out_size)
{
    const float* x      = (const float*)d_in[0];
    const float* p_w    = (const float*)d_in[1];
    const float* p_b    = (const float*)d_in[2];
    const float* m_w    = (const float*)d_in[3];
    const float* m_b    = (const float*)d_in[4];
    const float* conv_w = (const float*)d_in[5];
    const float* comp_w = (const float*)d_in[6];
    const float* spec_w = (const float*)d_in[7];
    const float* bn_g   = (const float*)d_in[8];
    const float* bn_b   = (const float*)d_in[9];
    float* out = (float*)d_out;

    cudaFuncSetAttribute(k_offmask, cudaFuncAttributeMaxDynamicSharedMemorySize, SMEM2_BYTES);
    cudaFuncSetAttribute(k_main,    cudaFuncAttributeMaxDynamicSharedMemorySize, SMEM3_BYTES);

    // 1a/1b. padded + reindexed input (two launches -> k_main is launch #4)
    k_pad_a<<<(PAD_HALF + 255) / 256, 256>>>(x);
    k_pad_b<<<(PAD_TOTAL - PAD_HALF + 255) / 256, 256>>>(x);
    // 2. offset + mask conv
    k_offmask<<<dim3(4, 4, NB), 256, SMEM2_BYTES>>>(p_w, p_b, m_w, m_b);
    // 3. deform sample + einsum + comp (persistent) -- launch #4, gets profiled
    k_main<<<152, NT3, SMEM3_BYTES>>>(conv_w, comp_w);
    // 4. spec conv + BN partials
    k_spec<<<SPEC_BLOCKS, 256>>>(spec_w);
    // 5. BN stats
    k_stats<<<16, 256>>>(bn_g, bn_b);
    // 6. normalize + relu
    {
        int total4 = (BB * TT * CC * HWSZ) / 4;
        k_final<<<(total4 + 255) / 256, 256>>>(out);
    }
}